// round 15
// baseline (speedup 1.0000x reference)
#include <cuda_runtime.h>
#include <cuda_fp16.h>
#include <cstdint>
#include <cstddef>

// Problem sizes (fixed)
#define BATCH 4096
#define HDIM  1024
#define KDIM  1024
#define NDIM  4096

// ---------------------------------------------------------------------------
// Scratch (device globals -- allocation is forbidden)
// ---------------------------------------------------------------------------
__device__ __align__(1024) __half g_xh [BATCH * KDIM];
__device__ __align__(1024) __half g_hh [BATCH * KDIM];
__device__ __align__(1024) __half g_wih[NDIM  * KDIM];
__device__ __align__(1024) __half g_whh[NDIM  * KDIM];
__device__ __align__(16) __half g_pre_ih[(size_t)BATCH * NDIM];   // fp16 pre-activations
__device__ __align__(16) __half g_pre_hh[(size_t)BATCH * NDIM];

// ---------------------------------------------------------------------------
// fp32 -> fp16 preconversion.  (FROZEN)
// ---------------------------------------------------------------------------
__global__ void __launch_bounds__(256) cvt_kernel(
    const float4* __restrict__ x, const float4* __restrict__ h,
    const float4* __restrict__ wih, const float4* __restrict__ whh)
{
    int i = blockIdx.x * blockDim.x + threadIdx.x;
    const float4* src; __half* dst;
    switch (blockIdx.y) {
        case 0:  src = x;   dst = g_xh;  break;
        case 1:  src = h;   dst = g_hh;  break;
        case 2:  src = wih; dst = g_wih; break;
        default: src = whh; dst = g_whh; break;
    }
    float4 v0 = src[4 * i];
    float4 v1 = src[4 * i + 1];
    float4 v2 = src[4 * i + 2];
    float4 v3 = src[4 * i + 3];
    __half2 o[8];
    o[0] = __floats2half2_rn(v0.x, v0.y);  o[1] = __floats2half2_rn(v0.z, v0.w);
    o[2] = __floats2half2_rn(v1.x, v1.y);  o[3] = __floats2half2_rn(v1.z, v1.w);
    o[4] = __floats2half2_rn(v2.x, v2.y);  o[5] = __floats2half2_rn(v2.z, v2.w);
    o[6] = __floats2half2_rn(v3.x, v3.y);  o[7] = __floats2half2_rn(v3.z, v3.w);
    uint4* d = (uint4*)(dst + 16 * (size_t)i);
    d[0] = ((uint4*)o)[0];
    d[1] = ((uint4*)o)[1];
}

// ---------------------------------------------------------------------------
// fp16 GEMM: C = A @ W^T.  128x128x32 tile, 64x32 warp tile, 4-stage cp.async,
// mbarrier pipeline (R14).  NEW: per-k-tile fp16 accumulation (mma f16.f16)
// folded into persistent fp32 accumulators each window (2x HMMA rate probe).
// grid = (N/128, M/128, 2).  block = 256 (8 warps, 2 CTA/SM)
// ---------------------------------------------------------------------------
#define BM 128
#define BN 128
#define BK 32
#define ROWB 80
#define STAGES 4
#define NK (KDIM / BK)
#define A_SM_BYTES (BM * ROWB)
#define STAGE_BYTES (2 * A_SM_BYTES)       // 20480
#define TILES_BYTES (STAGES * STAGE_BYTES) // 81920
#define SMEM_TOTAL (TILES_BYTES + 128)

__device__ __forceinline__ uint32_t smem_u32(const void* p) {
    uint32_t a;
    asm("{ .reg .u64 t; cvta.to.shared.u64 t, %1; cvt.u32.u64 %0, t; }" : "=r"(a) : "l"(p));
    return a;
}
__device__ __forceinline__ void cp16(uint32_t smem, const void* gmem) {
    asm volatile("cp.async.cg.shared.global [%0], [%1], 16;" :: "r"(smem), "l"(gmem));
}
#define LDSM_X4(r0, r1, r2, r3, addr) \
    asm volatile("ldmatrix.sync.aligned.m8n8.x4.shared.b16 {%0,%1,%2,%3}, [%4];" \
        : "=r"(r0), "=r"(r1), "=r"(r2), "=r"(r3) : "r"(addr))

// f16-accumulate MMA, C = zero regs (window start, ks0)
#define MMA_F16_Z(d, ar, br, z0) \
    asm volatile( \
        "mma.sync.aligned.m16n8k16.row.col.f16.f16.f16.f16 " \
        "{%0,%1}, {%2,%3,%4,%5}, {%6,%7}, {%8,%9};" \
        : "=r"((d)[0]), "=r"((d)[1]) \
        : "r"((ar)[0]), "r"((ar)[1]), "r"((ar)[2]), "r"((ar)[3]), \
          "r"((br)[0]), "r"((br)[1]), "r"(z0), "r"(z0))
// f16-accumulate MMA, D = A*B + D (chained, ks1)
#define MMA_F16_C(d, ar, br) \
    asm volatile( \
        "mma.sync.aligned.m16n8k16.row.col.f16.f16.f16.f16 " \
        "{%0,%1}, {%2,%3,%4,%5}, {%6,%7}, {%0,%1};" \
        : "+r"((d)[0]), "+r"((d)[1]) \
        : "r"((ar)[0]), "r"((ar)[1]), "r"((ar)[2]), "r"((ar)[3]), \
          "r"((br)[0]), "r"((br)[1]))

#define MBAR_INIT(addr, cnt) \
    asm volatile("mbarrier.init.shared.b64 [%0], %1;" :: "r"(addr), "r"(cnt) : "memory")
#define MBAR_ARRIVE(addr) \
    asm volatile("mbarrier.arrive.shared.b64 _, [%0];" :: "r"(addr) : "memory")
#define CPASYNC_MBAR_ARRIVE(addr) \
    asm volatile("cp.async.mbarrier.arrive.noinc.shared.b64 [%0];" :: "r"(addr) : "memory")
#define MBAR_WAIT(addr, ph) do { \
    uint32_t _m = (addr); uint32_t _p = (ph); uint32_t _d; \
    asm volatile("{\n\t.reg .pred p;\n\t" \
        "mbarrier.try_wait.parity.acquire.cta.shared::cta.b64 p, [%1], %2;\n\t" \
        "selp.b32 %0, 1, 0, p;\n\t}" : "=r"(_d) : "r"(_m), "r"(_p) : "memory"); \
    if (!_d) { \
        asm volatile("{\n\t.reg .pred P1;\n\t" \
            "WL_%=:\n\t" \
            "mbarrier.try_wait.parity.acquire.cta.shared::cta.b64 P1, [%0], %1, 0x989680;\n\t" \
            "@P1 bra.uni WD_%=;\n\t" \
            "bra.uni WL_%=;\n\t" \
            "WD_%=:\n\t}" :: "r"(_m), "r"(_p) : "memory"); \
    } \
} while (0)

__global__ void __launch_bounds__(256, 2) gemm_f16()
{
    extern __shared__ char smem[];
    const uint32_t sb = smem_u32(smem);
    const uint32_t mb_full  = sb + TILES_BYTES;
    const uint32_t mb_empty = sb + TILES_BYTES + 32;
    const int tid  = threadIdx.x;
    const int lane = tid & 31;
    const int warp = tid >> 5;
    const int wm   = warp >> 2;
    const int wn   = warp & 3;

    const int z = blockIdx.z;
    const __half* __restrict__ A = z ? g_hh  : g_xh;
    const __half* __restrict__ W = z ? g_whh : g_wih;
    __half* __restrict__ C       = z ? g_pre_hh : g_pre_ih;
    const int bm = blockIdx.y * BM;
    const int bn = blockIdx.x * BN;

    if (tid == 0) {
#pragma unroll
        for (int s = 0; s < STAGES; s++) {
            MBAR_INIT(mb_full  + 8 * s, 256);
            MBAR_INIT(mb_empty + 8 * s, 8);
        }
    }
    __syncthreads();

    float acc[4][4][4];
#pragma unroll
    for (int a = 0; a < 4; a++)
#pragma unroll
        for (int b = 0; b < 4; b++)
#pragma unroll
            for (int d = 0; d < 4; d++) acc[a][b][d] = 0.f;

    const uint32_t zreg = 0;   // fp16x2 zero for window-start C

    const int lrow = tid >> 1;
    const int lcp  = (tid & 1) * 2;
    const __half* gA0 = A + (size_t)(bm + lrow) * KDIM + lcp * 8;
    const __half* gW0 = W + (size_t)(bn + lrow) * KDIM + lcp * 8;
    const uint32_t sA0 = sb + lrow * ROWB + lcp * 16;
    const uint32_t sB0 = sA0 + A_SM_BYTES;

    auto issue = [&](int t) {
        const size_t ko = (size_t)t * BK;
        const uint32_t so = (t & (STAGES - 1)) * STAGE_BYTES;
        cp16(sA0 + so,      gA0 + ko);
        cp16(sA0 + so + 16, gA0 + ko + 8);
        cp16(sB0 + so,      gW0 + ko);
        cp16(sB0 + so + 16, gW0 + ko + 8);
        CPASYNC_MBAR_ARRIVE(mb_full + 8 * (t & (STAGES - 1)));
    };

    issue(0); issue(1); issue(2);

    const int l15 = lane & 15, lhi = lane >> 4;
    const uint32_t aBase = sb + (wm * 64 + l15) * ROWB + lhi * 16;
    const uint32_t bBase = sb + A_SM_BYTES + (wn * 32 + l15) * ROWB + lhi * 16;

    for (int kt = 0; kt < NK; kt++) {
        const uint32_t so = (kt & (STAGES - 1)) * STAGE_BYTES;
        MBAR_WAIT(mb_full + 8 * (kt & (STAGES - 1)), (kt >> 2) & 1);

        uint32_t acc16[4][4][2];   // fp16x2 window accumulators

#pragma unroll
        for (int ks = 0; ks < 2; ks++) {
            uint32_t a[4][4], b[4][2];
#pragma unroll
            for (int mt = 0; mt < 4; mt++)
                LDSM_X4(a[mt][0], a[mt][1], a[mt][2], a[mt][3],
                        aBase + so + mt * (16 * ROWB) + ks * 32);
            LDSM_X4(b[0][0], b[1][0], b[0][1], b[1][1], bBase + so + ks * 32);
            LDSM_X4(b[2][0], b[3][0], b[2][1], b[3][1],
                    bBase + so + 16 * ROWB + ks * 32);

            if (ks == 0) {
#pragma unroll
                for (int mt = 0; mt < 4; mt++)
#pragma unroll
                    for (int nt = 0; nt < 4; nt++)
                        MMA_F16_Z(acc16[mt][nt], a[mt], b[nt], zreg);
            } else {
#pragma unroll
                for (int mt = 0; mt < 4; mt++)
#pragma unroll
                    for (int nt = 0; nt < 4; nt++)
                        MMA_F16_C(acc16[mt][nt], a[mt], b[nt]);
            }
        }

        // fold window fp16 accumulators into fp32
#pragma unroll
        for (int mt = 0; mt < 4; mt++)
#pragma unroll
            for (int nt = 0; nt < 4; nt++) {
                float2 lo = __half22float2(*(__half2*)&acc16[mt][nt][0]);
                float2 hi = __half22float2(*(__half2*)&acc16[mt][nt][1]);
                acc[mt][nt][0] += lo.x;
                acc[mt][nt][1] += lo.y;
                acc[mt][nt][2] += hi.x;
                acc[mt][nt][3] += hi.y;
            }

        if (lane == 0) MBAR_ARRIVE(mb_empty + 8 * (kt & (STAGES - 1)));

        if (kt + 3 < NK) {
            const int t = kt + 3;
            if (t >= STAGES)
                MBAR_WAIT(mb_empty + 8 * (t & (STAGES - 1)),
                          ((t - STAGES) >> 2) & 1);
            issue(t);
        }
    }

    // epilogue: fp32 acc -> fp16 store
#pragma unroll
    for (int mt = 0; mt < 4; mt++) {
#pragma unroll
        for (int nt = 0; nt < 4; nt++) {
            int gm = bm + wm * 64 + mt * 16 + (lane >> 2);
            int gn = bn + wn * 32 + nt * 8 + (lane & 3) * 2;
            *(__half2*)&C[(size_t)gm * NDIM + gn] =
                __floats2half2_rn(acc[mt][nt][0], acc[mt][nt][1]);
            *(__half2*)&C[(size_t)(gm + 8) * NDIM + gn] =
                __floats2half2_rn(acc[mt][nt][2], acc[mt][nt][3]);
        }
    }
}

// ---------------------------------------------------------------------------
// LayerNorm + LSTM cell: single-pass, register-resident.  (R12, FROZEN)
// ---------------------------------------------------------------------------
__device__ __forceinline__ float tanh_ap(float x) {
    float y;
    asm("tanh.approx.f32 %0, %1;" : "=f"(y) : "f"(x));
    return y;
}
__device__ __forceinline__ float sigmoid_ap(float x) {
    return fmaf(tanh_ap(0.5f * x), 0.5f, 0.5f);
}

__global__ void __launch_bounds__(256) ln_cell_kernel(
    const float* __restrict__ c_in,
    const float* __restrict__ b_ih,
    const float* __restrict__ gma,
    const float* __restrict__ bta,
    float* __restrict__ out)
{
    const int b    = blockIdx.x;
    const int tid  = threadIdx.x;
    const int warp = tid >> 5, lane = tid & 31;

    __shared__ float psums[16][256];
    __shared__ float stats[18];
    __shared__ float red[16];

    const uint2* pih2 = (const uint2*)(g_pre_ih + (size_t)b * NDIM);
    const uint2* phh2 = (const uint2*)(g_pre_hh + (size_t)b * NDIM);

    float vih[4][4], vhh[4][4];
    float sum[8], ssq[8];
#pragma unroll
    for (int g = 0; g < 4; g++) {
        uint2 ri = pih2[g * 256 + tid];
        uint2 rh = phh2[g * 256 + tid];
        float2 f0 = __half22float2(*(__half2*)&ri.x);
        float2 f1 = __half22float2(*(__half2*)&ri.y);
        vih[g][0] = f0.x; vih[g][1] = f0.y; vih[g][2] = f1.x; vih[g][3] = f1.y;
        sum[2*g] = f0.x + f0.y + f1.x + f1.y;
        ssq[2*g] = f0.x*f0.x + f0.y*f0.y + f1.x*f1.x + f1.y*f1.y;
        f0 = __half22float2(*(__half2*)&rh.x);
        f1 = __half22float2(*(__half2*)&rh.y);
        vhh[g][0] = f0.x; vhh[g][1] = f0.y; vhh[g][2] = f1.x; vhh[g][3] = f1.y;
        sum[2*g+1] = f0.x + f0.y + f1.x + f1.y;
        ssq[2*g+1] = f0.x*f0.x + f0.y*f0.y + f1.x*f1.x + f1.y*f1.y;
    }

#pragma unroll
    for (int s = 0; s < 8; s++) {
        psums[2*s][tid]     = sum[s];
        psums[2*s + 1][tid] = ssq[s];
    }
    __syncthreads();

    {
        float as = 0.f, aq = 0.f;
#pragma unroll
        for (int k = 0; k < 8; k++) {
            as += psums[2*warp][lane + 32*k];
            aq += psums[2*warp + 1][lane + 32*k];
        }
#pragma unroll
        for (int o = 16; o; o >>= 1) {
            as += __shfl_xor_sync(0xffffffffu, as, o);
            aq += __shfl_xor_sync(0xffffffffu, aq, o);
        }
        if (lane == 0) {
            float mu = as * (1.0f / HDIM);
            stats[2*warp]     = mu;
            stats[2*warp + 1] = aq * (1.0f / HDIM) - mu * mu;
        }
    }
    __syncthreads();

    float mu[8], rs[8];
#pragma unroll
    for (int t = 0; t < 8; t++) {
        mu[t] = stats[2*t];
        rs[t] = rsqrtf(stats[2*t + 1] + 1e-5f);
    }

    const float4* g4  = (const float4*)gma;
    const float4* bt4 = (const float4*)bta;
    const float4* bi4 = (const float4*)b_ih;

    float act[4][4];
#pragma unroll
    for (int g = 0; g < 4; g++) {
        float4 Gi = g4 [(2*g) * 256 + tid];
        float4 Bi = bt4[(2*g) * 256 + tid];
        float4 Gh = g4 [(2*g + 1) * 256 + tid];
        float4 Bh = bt4[(2*g + 1) * 256 + tid];
        float4 Fb = bi4[g * 256 + tid];
        const float* gi = (const float*)&Gi;  const float* bi = (const float*)&Bi;
        const float* gh = (const float*)&Gh;  const float* bh = (const float*)&Bh;
        const float* fb = (const float*)&Fb;
#pragma unroll
        for (int jj = 0; jj < 4; jj++) {
            float li = gi[jj] * (vih[g][jj] - mu[2*g])     * rs[2*g]     + bi[jj];
            float lh = gh[jj] * (vhh[g][jj] - mu[2*g + 1]) * rs[2*g + 1] + bh[jj];
            act[g][jj] = li + lh + fb[jj];
        }
    }

    float4 c4 = ((const float4*)(c_in + (size_t)b * HDIM))[tid];
    const float* cp = (const float*)&c4;
    float cvals[4], ovals[4];
    float csum = 0.f, css = 0.f;
#pragma unroll
    for (int jj = 0; jj < 4; jj++) {
        float ig = sigmoid_ap(act[0][jj]);
        float fg = sigmoid_ap(act[1][jj]);
        float ag = tanh_ap(act[2][jj]);
        float cn = fg * cp[jj] + ig * ag;
        cvals[jj] = cn;
        ovals[jj] = act[3][jj];
        csum += cn; css += cn * cn;
    }

#pragma unroll
    for (int o = 16; o; o >>= 1) {
        csum += __shfl_xor_sync(0xffffffffu, csum, o);
        css  += __shfl_xor_sync(0xffffffffu, css,  o);
    }
    if (lane == 0) { red[warp] = csum; red[8 + warp] = css; }
    __syncthreads();
    if (tid == 0) {
        float s = 0.f, q = 0.f;
#pragma unroll
        for (int k = 0; k < 8; k++) { s += red[k]; q += red[8 + k]; }
        float m = s * (1.0f / HDIM);
        stats[16] = m;
        stats[17] = q * (1.0f / HDIM) - m * m;
    }
    __syncthreads();

    const float cmu = stats[16];
    const float crs = rsqrtf(stats[17] + 1e-5f);

    float4 Gc = g4 [8 * 256 + tid];
    float4 Bc = bt4[8 * 256 + tid];
    const float* gc = (const float*)&Gc;
    const float* bc = (const float*)&Bc;

    float4 hn4, cn4;
    float* hn = (float*)&hn4;  float* cn = (float*)&cn4;
#pragma unroll
    for (int jj = 0; jj < 4; jj++) {
        float lnc = gc[jj] * (cvals[jj] - cmu) * crs + bc[jj];
        hn[jj] = sigmoid_ap(ovals[jj]) * tanh_ap(lnc);
        cn[jj] = cvals[jj];
    }
    float4* out4 = (float4*)out;
    out4[(size_t)b * 256 + tid] = hn4;
    out4[(size_t)BATCH * 256 + (size_t)b * 256 + tid] = cn4;
}

// ---------------------------------------------------------------------------
// kernel_launch
// ---------------------------------------------------------------------------
extern "C" void kernel_launch(void* const* d_in, const int* in_sizes, int n_in,
                              void* d_out, int out_size)
{
    const float* x   = (const float*)d_in[0];
    const float* h   = (const float*)d_in[1];
    const float* c   = (const float*)d_in[2];
    const float* wih = (const float*)d_in[3];
    const float* whh = (const float*)d_in[4];
    const float* bih = (const float*)d_in[5];
    const float* gma = (const float*)d_in[6];
    const float* bta = (const float*)d_in[7];
    float* out = (float*)d_out;

    dim3 cgrid(BATCH * KDIM / 16 / 256, 4);
    cvt_kernel<<<cgrid, 256>>>((const float4*)x, (const float4*)h,
                               (const float4*)wih, (const float4*)whh);

    cudaFuncSetAttribute(gemm_f16, cudaFuncAttributeMaxDynamicSharedMemorySize, SMEM_TOTAL);
    dim3 ggrid(NDIM / BN, BATCH / BM, 2);
    gemm_f16<<<ggrid, 256, SMEM_TOTAL>>>();

    ln_cell_kernel<<<BATCH, 256>>>(c, bih, gma, bta, out);
}

// round 16
// speedup vs baseline: 1.1881x; 1.1881x over previous
#include <cuda_runtime.h>
#include <cuda_fp16.h>
#include <cstdint>
#include <cstddef>

// Problem sizes (fixed)
#define BATCH 4096
#define HDIM  1024
#define KDIM  1024
#define NDIM  4096

// ---------------------------------------------------------------------------
// Scratch (device globals -- allocation is forbidden)
// ---------------------------------------------------------------------------
__device__ __align__(1024) __half g_xh [BATCH * KDIM];
__device__ __align__(1024) __half g_hh [BATCH * KDIM];
__device__ __align__(1024) __half g_wih[NDIM  * KDIM];
__device__ __align__(1024) __half g_whh[NDIM  * KDIM];
__device__ __align__(16) __half g_pre_ih[(size_t)BATCH * NDIM];
__device__ __align__(16) __half g_pre_hh[(size_t)BATCH * NDIM];
__device__ unsigned int g_cnt[2];   // cvt completion counters (reset by ln_cell)

// ---------------------------------------------------------------------------
// Fused kernel: 1D grid of 3072 blocks, 256 threads.
//   [0,512)      cvt x + w_ih      -> g_cnt[0]
//   [512,1536)   GEMM ih  (spins on g_cnt[0] == 512)
//   [1536,2048)  cvt h + w_hh      -> g_cnt[1]   (overlaps GEMM ih)
//   [2048,3072)  GEMM hh  (spins on g_cnt[1] == 512)
// GEMM body = R14 (mbarrier pipeline, noinc cp.async arrive, LDSM preload).
// ---------------------------------------------------------------------------
#define BM 128
#define BN 128
#define BK 32
#define ROWB 80
#define STAGES 4
#define NK (KDIM / BK)
#define A_SM_BYTES (BM * ROWB)
#define STAGE_BYTES (2 * A_SM_BYTES)       // 20480
#define TILES_BYTES (STAGES * STAGE_BYTES) // 81920
#define SMEM_TOTAL (TILES_BYTES + 128)

__device__ __forceinline__ uint32_t smem_u32(const void* p) {
    uint32_t a;
    asm("{ .reg .u64 t; cvta.to.shared.u64 t, %1; cvt.u32.u64 %0, t; }" : "=r"(a) : "l"(p));
    return a;
}
__device__ __forceinline__ void cp16(uint32_t smem, const void* gmem) {
    asm volatile("cp.async.cg.shared.global [%0], [%1], 16;" :: "r"(smem), "l"(gmem));
}
#define LDSM_X4(r0, r1, r2, r3, addr) \
    asm volatile("ldmatrix.sync.aligned.m8n8.x4.shared.b16 {%0,%1,%2,%3}, [%4];" \
        : "=r"(r0), "=r"(r1), "=r"(r2), "=r"(r3) : "r"(addr))
#define MMA16816(acc, ar, br) \
    asm volatile( \
        "mma.sync.aligned.m16n8k16.row.col.f32.f16.f16.f32 " \
        "{%0,%1,%2,%3}, {%4,%5,%6,%7}, {%8,%9}, {%0,%1,%2,%3};" \
        : "+f"((acc)[0]), "+f"((acc)[1]), "+f"((acc)[2]), "+f"((acc)[3]) \
        : "r"((ar)[0]), "r"((ar)[1]), "r"((ar)[2]), "r"((ar)[3]), \
          "r"((br)[0]), "r"((br)[1]))

#define MBAR_INIT(addr, cnt) \
    asm volatile("mbarrier.init.shared.b64 [%0], %1;" :: "r"(addr), "r"(cnt) : "memory")
#define MBAR_ARRIVE(addr) \
    asm volatile("mbarrier.arrive.shared.b64 _, [%0];" :: "r"(addr) : "memory")
#define CPASYNC_MBAR_ARRIVE(addr) \
    asm volatile("cp.async.mbarrier.arrive.noinc.shared.b64 [%0];" :: "r"(addr) : "memory")
#define MBAR_WAIT(addr, ph) do { \
    uint32_t _m = (addr); uint32_t _p = (ph); uint32_t _d; \
    asm volatile("{\n\t.reg .pred p;\n\t" \
        "mbarrier.try_wait.parity.acquire.cta.shared::cta.b64 p, [%1], %2;\n\t" \
        "selp.b32 %0, 1, 0, p;\n\t}" : "=r"(_d) : "r"(_m), "r"(_p) : "memory"); \
    if (!_d) { \
        asm volatile("{\n\t.reg .pred P1;\n\t" \
            "WL_%=:\n\t" \
            "mbarrier.try_wait.parity.acquire.cta.shared::cta.b64 P1, [%0], %1, 0x989680;\n\t" \
            "@P1 bra.uni WD_%=;\n\t" \
            "bra.uni WL_%=;\n\t" \
            "WD_%=:\n\t}" :: "r"(_m), "r"(_p) : "memory"); \
    } \
} while (0)

__global__ void __launch_bounds__(256, 2) fused_kernel(
    const float4* __restrict__ x, const float4* __restrict__ h,
    const float4* __restrict__ wih, const float4* __restrict__ whh)
{
    const int bid = blockIdx.x;
    const int tid = threadIdx.x;

    // ------------------------- cvt segments -------------------------
    if (bid < 512 || (bid >= 1536 && bid < 2048)) {
        const int seg   = (bid < 512) ? 0 : 1;
        const int local = (bid < 512) ? bid : bid - 1536;
        const int tensor = local >> 8;          // 0: activation, 1: weight
        const int chunk  = local & 255;
        const float4* src;
        __half* dst;
        if (seg == 0) { src = tensor ? wih : x; dst = tensor ? g_wih : g_xh; }
        else          { src = tensor ? whh : h; dst = tensor ? g_whh : g_hh; }

        const int base = chunk * 256 + tid;     // pair index base (8 floats/pair)
#pragma unroll
        for (int q = 0; q < 8; q++) {
            int p = base + q * 65536;
            float4 a = src[2 * p];
            float4 b = src[2 * p + 1];
            __half2 o[4];
            o[0] = __floats2half2_rn(a.x, a.y);
            o[1] = __floats2half2_rn(a.z, a.w);
            o[2] = __floats2half2_rn(b.x, b.y);
            o[3] = __floats2half2_rn(b.z, b.w);
            ((uint4*)dst)[p] = *(uint4*)o;
        }
        __threadfence();
        __syncthreads();
        if (tid == 0) atomicAdd(&g_cnt[seg], 1u);
        return;
    }

    // ------------------------- GEMM segments -------------------------
    const int z = (bid >= 2048) ? 1 : 0;
    const int t = z ? (bid - 2048) : (bid - 512);
    const int bm = (t >> 5) * BM;
    const int bn = (t & 31) * BN;

    extern __shared__ char smem[];
    const uint32_t sb = smem_u32(smem);
    const uint32_t mb_full  = sb + TILES_BYTES;
    const uint32_t mb_empty = sb + TILES_BYTES + 32;
    const int lane = tid & 31;
    const int warp = tid >> 5;
    const int wm   = warp >> 2;
    const int wn   = warp & 3;

    const __half* __restrict__ A = z ? g_hh  : g_xh;
    const __half* __restrict__ W = z ? g_whh : g_wih;
    __half* __restrict__ C       = z ? g_pre_hh : g_pre_ih;

    if (tid == 0) {
        // wait for this GEMM's cvt segment to finish (in-order dispatch: the
        // cvt blocks have lower bids, so they are dispatched first and finish)
        while (atomicAdd(&g_cnt[z], 0u) < 512u) __nanosleep(64);
        __threadfence();
#pragma unroll
        for (int s = 0; s < STAGES; s++) {
            MBAR_INIT(mb_full  + 8 * s, 256);
            MBAR_INIT(mb_empty + 8 * s, 8);
        }
    }
    __syncthreads();

    float acc[4][4][4];
#pragma unroll
    for (int a = 0; a < 4; a++)
#pragma unroll
        for (int b = 0; b < 4; b++)
#pragma unroll
            for (int d = 0; d < 4; d++) acc[a][b][d] = 0.f;

    const int lrow = tid >> 1;
    const int lcp  = (tid & 1) * 2;
    const __half* gA0 = A + (size_t)(bm + lrow) * KDIM + lcp * 8;
    const __half* gW0 = W + (size_t)(bn + lrow) * KDIM + lcp * 8;
    const uint32_t sA0 = sb + lrow * ROWB + lcp * 16;
    const uint32_t sB0 = sA0 + A_SM_BYTES;

    auto issue = [&](int kt) {
        const size_t ko = (size_t)kt * BK;
        const uint32_t so = (kt & (STAGES - 1)) * STAGE_BYTES;
        cp16(sA0 + so,      gA0 + ko);
        cp16(sA0 + so + 16, gA0 + ko + 8);
        cp16(sB0 + so,      gW0 + ko);
        cp16(sB0 + so + 16, gW0 + ko + 8);
        CPASYNC_MBAR_ARRIVE(mb_full + 8 * (kt & (STAGES - 1)));
    };

    issue(0); issue(1); issue(2);

    const int l15 = lane & 15, lhi = lane >> 4;
    const uint32_t aBase = sb + (wm * 64 + l15) * ROWB + lhi * 16;
    const uint32_t bBase = sb + A_SM_BYTES + (wn * 32 + l15) * ROWB + lhi * 16;

    MBAR_WAIT(mb_full + 0, 0);
    uint32_t a0[4][4], b0[4][2];
#pragma unroll
    for (int mt = 0; mt < 4; mt++)
        LDSM_X4(a0[mt][0], a0[mt][1], a0[mt][2], a0[mt][3],
                aBase + mt * (16 * ROWB));
    LDSM_X4(b0[0][0], b0[1][0], b0[0][1], b0[1][1], bBase);
    LDSM_X4(b0[2][0], b0[3][0], b0[2][1], b0[3][1], bBase + 16 * ROWB);

    for (int kt = 0; kt < NK; kt++) {
        const uint32_t so  = (kt & (STAGES - 1)) * STAGE_BYTES;
        const uint32_t son = ((kt + 1) & (STAGES - 1)) * STAGE_BYTES;

        uint32_t a1[4][4], b1[4][2];
#pragma unroll
        for (int mt = 0; mt < 4; mt++)
            LDSM_X4(a1[mt][0], a1[mt][1], a1[mt][2], a1[mt][3],
                    aBase + so + mt * (16 * ROWB) + 32);
        LDSM_X4(b1[0][0], b1[1][0], b1[0][1], b1[1][1], bBase + so + 32);
        LDSM_X4(b1[2][0], b1[3][0], b1[2][1], b1[3][1],
                bBase + so + 16 * ROWB + 32);

#pragma unroll
        for (int mt = 0; mt < 4; mt++)
#pragma unroll
            for (int nt = 0; nt < 4; nt++)
                MMA16816(acc[mt][nt], a0[mt], b0[nt]);

        if (kt + 1 < NK) {
            MBAR_WAIT(mb_full + 8 * ((kt + 1) & (STAGES - 1)),
                      ((kt + 1) >> 2) & 1);
#pragma unroll
            for (int mt = 0; mt < 4; mt++)
                LDSM_X4(a0[mt][0], a0[mt][1], a0[mt][2], a0[mt][3],
                        aBase + son + mt * (16 * ROWB));
            LDSM_X4(b0[0][0], b0[1][0], b0[0][1], b0[1][1], bBase + son);
            LDSM_X4(b0[2][0], b0[3][0], b0[2][1], b0[3][1],
                    bBase + son + 16 * ROWB);
        }

#pragma unroll
        for (int mt = 0; mt < 4; mt++)
#pragma unroll
            for (int nt = 0; nt < 4; nt++)
                MMA16816(acc[mt][nt], a1[mt], b1[nt]);

        if (lane == 0) MBAR_ARRIVE(mb_empty + 8 * (kt & (STAGES - 1)));

        if (kt + 3 < NK) {
            const int tt = kt + 3;
            if (tt >= STAGES)
                MBAR_WAIT(mb_empty + 8 * (tt & (STAGES - 1)),
                          ((tt - STAGES) >> 2) & 1);
            issue(tt);
        }
    }

#pragma unroll
    for (int mt = 0; mt < 4; mt++) {
#pragma unroll
        for (int nt = 0; nt < 4; nt++) {
            int gm = bm + wm * 64 + mt * 16 + (lane >> 2);
            int gn = bn + wn * 32 + nt * 8 + (lane & 3) * 2;
            *(__half2*)&C[(size_t)gm * NDIM + gn] =
                __floats2half2_rn(acc[mt][nt][0], acc[mt][nt][1]);
            *(__half2*)&C[(size_t)(gm + 8) * NDIM + gn] =
                __floats2half2_rn(acc[mt][nt][2], acc[mt][nt][3]);
        }
    }
}

// ---------------------------------------------------------------------------
// LayerNorm + LSTM cell: single-pass, register-resident.  (R12, FROZEN)
// Also resets the cvt counters for the next graph replay.
// ---------------------------------------------------------------------------
__device__ __forceinline__ float tanh_ap(float x) {
    float y;
    asm("tanh.approx.f32 %0, %1;" : "=f"(y) : "f"(x));
    return y;
}
__device__ __forceinline__ float sigmoid_ap(float x) {
    return fmaf(tanh_ap(0.5f * x), 0.5f, 0.5f);
}

__global__ void __launch_bounds__(256) ln_cell_kernel(
    const float* __restrict__ c_in,
    const float* __restrict__ b_ih,
    const float* __restrict__ gma,
    const float* __restrict__ bta,
    float* __restrict__ out)
{
    const int b    = blockIdx.x;
    const int tid  = threadIdx.x;
    const int warp = tid >> 5, lane = tid & 31;

    if (b == 0 && tid == 0) { g_cnt[0] = 0; g_cnt[1] = 0; }   // reset for replay

    __shared__ float psums[16][256];
    __shared__ float stats[18];
    __shared__ float red[16];

    const uint2* pih2 = (const uint2*)(g_pre_ih + (size_t)b * NDIM);
    const uint2* phh2 = (const uint2*)(g_pre_hh + (size_t)b * NDIM);

    float vih[4][4], vhh[4][4];
    float sum[8], ssq[8];
#pragma unroll
    for (int g = 0; g < 4; g++) {
        uint2 ri = pih2[g * 256 + tid];
        uint2 rh = phh2[g * 256 + tid];
        float2 f0 = __half22float2(*(__half2*)&ri.x);
        float2 f1 = __half22float2(*(__half2*)&ri.y);
        vih[g][0] = f0.x; vih[g][1] = f0.y; vih[g][2] = f1.x; vih[g][3] = f1.y;
        sum[2*g] = f0.x + f0.y + f1.x + f1.y;
        ssq[2*g] = f0.x*f0.x + f0.y*f0.y + f1.x*f1.x + f1.y*f1.y;
        f0 = __half22float2(*(__half2*)&rh.x);
        f1 = __half22float2(*(__half2*)&rh.y);
        vhh[g][0] = f0.x; vhh[g][1] = f0.y; vhh[g][2] = f1.x; vhh[g][3] = f1.y;
        sum[2*g+1] = f0.x + f0.y + f1.x + f1.y;
        ssq[2*g+1] = f0.x*f0.x + f0.y*f0.y + f1.x*f1.x + f1.y*f1.y;
    }

#pragma unroll
    for (int s = 0; s < 8; s++) {
        psums[2*s][tid]     = sum[s];
        psums[2*s + 1][tid] = ssq[s];
    }
    __syncthreads();

    {
        float as = 0.f, aq = 0.f;
#pragma unroll
        for (int k = 0; k < 8; k++) {
            as += psums[2*warp][lane + 32*k];
            aq += psums[2*warp + 1][lane + 32*k];
        }
#pragma unroll
        for (int o = 16; o; o >>= 1) {
            as += __shfl_xor_sync(0xffffffffu, as, o);
            aq += __shfl_xor_sync(0xffffffffu, aq, o);
        }
        if (lane == 0) {
            float mu = as * (1.0f / HDIM);
            stats[2*warp]     = mu;
            stats[2*warp + 1] = aq * (1.0f / HDIM) - mu * mu;
        }
    }
    __syncthreads();

    float mu[8], rs[8];
#pragma unroll
    for (int t = 0; t < 8; t++) {
        mu[t] = stats[2*t];
        rs[t] = rsqrtf(stats[2*t + 1] + 1e-5f);
    }

    const float4* g4  = (const float4*)gma;
    const float4* bt4 = (const float4*)bta;
    const float4* bi4 = (const float4*)b_ih;

    float act[4][4];
#pragma unroll
    for (int g = 0; g < 4; g++) {
        float4 Gi = g4 [(2*g) * 256 + tid];
        float4 Bi = bt4[(2*g) * 256 + tid];
        float4 Gh = g4 [(2*g + 1) * 256 + tid];
        float4 Bh = bt4[(2*g + 1) * 256 + tid];
        float4 Fb = bi4[g * 256 + tid];
        const float* gi = (const float*)&Gi;  const float* bi = (const float*)&Bi;
        const float* gh = (const float*)&Gh;  const float* bh = (const float*)&Bh;
        const float* fb = (const float*)&Fb;
#pragma unroll
        for (int jj = 0; jj < 4; jj++) {
            float li = gi[jj] * (vih[g][jj] - mu[2*g])     * rs[2*g]     + bi[jj];
            float lh = gh[jj] * (vhh[g][jj] - mu[2*g + 1]) * rs[2*g + 1] + bh[jj];
            act[g][jj] = li + lh + fb[jj];
        }
    }

    float4 c4 = ((const float4*)(c_in + (size_t)b * HDIM))[tid];
    const float* cp = (const float*)&c4;
    float cvals[4], ovals[4];
    float csum = 0.f, css = 0.f;
#pragma unroll
    for (int jj = 0; jj < 4; jj++) {
        float ig = sigmoid_ap(act[0][jj]);
        float fg = sigmoid_ap(act[1][jj]);
        float ag = tanh_ap(act[2][jj]);
        float cn = fg * cp[jj] + ig * ag;
        cvals[jj] = cn;
        ovals[jj] = act[3][jj];
        csum += cn; css += cn * cn;
    }

#pragma unroll
    for (int o = 16; o; o >>= 1) {
        csum += __shfl_xor_sync(0xffffffffu, csum, o);
        css  += __shfl_xor_sync(0xffffffffu, css,  o);
    }
    if (lane == 0) { red[warp] = csum; red[8 + warp] = css; }
    __syncthreads();
    if (tid == 0) {
        float s = 0.f, q = 0.f;
#pragma unroll
        for (int k = 0; k < 8; k++) { s += red[k]; q += red[8 + k]; }
        float m = s * (1.0f / HDIM);
        stats[16] = m;
        stats[17] = q * (1.0f / HDIM) - m * m;
    }
    __syncthreads();

    const float cmu = stats[16];
    const float crs = rsqrtf(stats[17] + 1e-5f);

    float4 Gc = g4 [8 * 256 + tid];
    float4 Bc = bt4[8 * 256 + tid];
    const float* gc = (const float*)&Gc;
    const float* bc = (const float*)&Bc;

    float4 hn4, cn4;
    float* hn = (float*)&hn4;  float* cn = (float*)&cn4;
#pragma unroll
    for (int jj = 0; jj < 4; jj++) {
        float lnc = gc[jj] * (cvals[jj] - cmu) * crs + bc[jj];
        hn[jj] = sigmoid_ap(ovals[jj]) * tanh_ap(lnc);
        cn[jj] = cvals[jj];
    }
    float4* out4 = (float4*)out;
    out4[(size_t)b * 256 + tid] = hn4;
    out4[(size_t)BATCH * 256 + (size_t)b * 256 + tid] = cn4;
}

// ---------------------------------------------------------------------------
// kernel_launch
// ---------------------------------------------------------------------------
extern "C" void kernel_launch(void* const* d_in, const int* in_sizes, int n_in,
                              void* d_out, int out_size)
{
    const float* x   = (const float*)d_in[0];
    const float* h   = (const float*)d_in[1];
    const float* c   = (const float*)d_in[2];
    const float* wih = (const float*)d_in[3];
    const float* whh = (const float*)d_in[4];
    const float* bih = (const float*)d_in[5];
    const float* gma = (const float*)d_in[6];
    const float* bta = (const float*)d_in[7];
    float* out = (float*)d_out;

    cudaFuncSetAttribute(fused_kernel, cudaFuncAttributeMaxDynamicSharedMemorySize, SMEM_TOTAL);
    fused_kernel<<<3072, 256, SMEM_TOTAL>>>(
        (const float4*)x, (const float4*)h,
        (const float4*)wih, (const float4*)whh);

    ln_cell_kernel<<<BATCH, 256>>>(c, bih, gma, bta, out);
}